// round 9
// baseline (speedup 1.0000x reference)
#include <cuda_runtime.h>
#include <math.h>
#include <float.h>

#define B   8
#define L   256
#define H   128
#define NH  4
#define D   32
#define NB  2
#define NROWS (B*L)

// ---------------- scratch (device globals; no allocation allowed) ------------
__device__ float g_x  [NROWS*H];
__device__ float g_q  [NROWS*H];
__device__ float g_Q  [NROWS*H];      // pre-scaled by log2(e)/sqrt(D)
__device__ float g_K  [NROWS*H];
__device__ float g_V  [NROWS*H];
__device__ float g_QA1[NROWS*NH*H];   // pre-scaled by log2(e)/sqrt(D)

__device__ __forceinline__ float dot4(float4 a, float4 b) {
    return a.x*b.x + a.y*b.y + a.z*b.z + a.w*b.w;
}

// ---------------- LN1 + QKV + QA1 projections (fused), 8 rows/CTA ------------
#define RQ 8
__global__ __launch_bounds__(128)
void qkv_kernel(const float* __restrict__ ext_src, int use_ext,
                const float* __restrict__ lng, const float* __restrict__ lnb,
                const float* __restrict__ Qw, const float* __restrict__ Qb,
                const float* __restrict__ Kw, const float* __restrict__ Kb,
                const float* __restrict__ Vw, const float* __restrict__ Vb,
                const float* __restrict__ WA1)
{
    __shared__ __align__(16) float qs[RQ][H];
    __shared__ __align__(16) float Qs[RQ][H];
    __shared__ float stat[RQ][2];
    int t = threadIdx.x;
    int row0 = blockIdx.x * RQ;
    int w = t >> 5, lane = t & 31;

    float v[RQ];
    #pragma unroll
    for (int r = 0; r < RQ; r++) {
        v[r] = use_ext ? ext_src[(row0+r)*H + t] : g_x[(row0+r)*H + t];
        qs[r][t] = v[r];
    }
    __syncthreads();

    // warp w reduces rows 2w and 2w+1
    #pragma unroll
    for (int rr = 0; rr < 2; rr++) {
        int r = w*2 + rr;
        float4 a = *(const float4*)(&qs[r][lane*4]);
        float s  = a.x + a.y + a.z + a.w;
        float sq = a.x*a.x + a.y*a.y + a.z*a.z + a.w*a.w;
        #pragma unroll
        for (int o = 16; o; o >>= 1) {
            s  += __shfl_xor_sync(0xffffffffu, s,  o);
            sq += __shfl_xor_sync(0xffffffffu, sq, o);
        }
        if (lane == 0) {
            float mean = s * (1.0f/H);
            float var  = sq * (1.0f/H) - mean*mean;
            stat[r][0] = mean;
            stat[r][1] = rsqrtf(var + 1e-8f);
        }
    }
    __syncthreads();

    float gam = lng[t], bet = lnb[t];
    #pragma unroll
    for (int r = 0; r < RQ; r++) {
        float q = (v[r] - stat[r][0]) * stat[r][1] * gam + bet;
        qs[r][t] = q;
        g_q[(row0+r)*H + t] = q;
    }
    __syncthreads();

    float aq[RQ], ak[RQ], av[RQ];
    #pragma unroll
    for (int r = 0; r < RQ; r++) { aq[r] = 0.f; ak[r] = 0.f; av[r] = 0.f; }
    const float* qwr = Qw + t*H;
    const float* kwr = Kw + t*H;
    const float* vwr = Vw + t*H;
    for (int k = 0; k < H; k += 4) {
        float4 wq = *(const float4*)(qwr + k);
        float4 wk = *(const float4*)(kwr + k);
        float4 wv = *(const float4*)(vwr + k);
        #pragma unroll
        for (int r = 0; r < RQ; r++) {
            float4 q4 = *(const float4*)(&qs[r][k]);
            aq[r] += q4.x*wq.x + q4.y*wq.y + q4.z*wq.z + q4.w*wq.w;
            ak[r] += q4.x*wk.x + q4.y*wk.y + q4.z*wk.z + q4.w*wk.w;
            av[r] += q4.x*wv.x + q4.y*wv.y + q4.z*wv.z + q4.w*wv.w;
        }
    }
    // 1/sqrt(32) * log2(e): fixed-base exp2 softmax downstream
    const float rs = 0.17677669529663687f * 1.4426950408889634f;
    float bq = Qb[t], bk = Kb[t], bv = Vb[t];
    #pragma unroll
    for (int r = 0; r < RQ; r++) {
        float Qv = (aq[r] + bq) * rs;
        Qs[r][t] = Qv;
        g_Q[(row0+r)*H + t] = Qv;
        g_K[(row0+r)*H + t] = ak[r] + bk;
        g_V[(row0+r)*H + t] = av[r] + bv;
    }
    __syncthreads();

    #pragma unroll
    for (int h = 0; h < NH; h++) {
        float a[RQ];
        #pragma unroll
        for (int r = 0; r < RQ; r++) a[r] = 0.f;
        const float* w1 = WA1 + h*D*H + t;
        for (int dd = 0; dd < D; dd += 4) {
            float w0 = w1[(dd+0)*H];
            float wA = w1[(dd+1)*H];
            float wB = w1[(dd+2)*H];
            float wC = w1[(dd+3)*H];
            #pragma unroll
            for (int r = 0; r < RQ; r++) {
                float4 q4 = *(const float4*)(&Qs[r][h*D + dd]);
                a[r] += q4.x*w0 + q4.y*wA + q4.z*wB + q4.w*wC;
            }
        }
        #pragma unroll
        for (int r = 0; r < RQ; r++)
            g_QA1[((row0+r)*NH + h)*H + t] = a[r];
    }
}

// ---------------- Attention v5: v3 body, balanced row-pairing ----------------
// CTA k handles rows (b, ii) and (b, L-1-ii): total work = L+1 j's, uniform.
// 256 threads: warps 0-3 -> row ii (head=warp), warps 4-7 -> mirror row.
// Fixed-base exp2, no online max (scores O(1); masked rows -> uniform weights;
// causal j>i -> w=0 exactly).
__global__ __launch_bounds__(256)
void attn_kernel(const float* __restrict__ tm,
                 const unsigned char* __restrict__ tmask,
                 const float* __restrict__ WA2)
{
    __shared__ __align__(16) float sS[2][NH][H];
    __shared__ __align__(16) float sV[2][NH][D];

    int kblk = blockIdx.x;
    int b    = kblk >> 7;            // L/2 = 128 pairs per batch
    int ii   = kblk & 127;
    int half = threadIdx.x >> 7;     // 0: row ii, 1: row L-1-ii
    int i    = half ? (L-1-ii) : ii;
    int row  = b*L + i;
    int t128 = threadIdx.x & 127;
    int lane = t128 & 31;
    int h    = t128 >> 5;
    int g    = lane >> 3;            // j within tile
    int c    = lane & 7;             // column octet

    const float* qaB = g_QA1 + (row*NH + h)*H + c*4;
    float4 qa0 = *(const float4*)(qaB);
    float4 qa1 = *(const float4*)(qaB + 32);
    float4 qa2 = *(const float4*)(qaB + 64);
    float4 qa3 = *(const float4*)(qaB + 96);
    float4 q4  = *(const float4*)(g_Q + row*H + h*D + c*4);

    bool rmask = tmask[row] != 0;
    int  limit = rmask ? (L-1) : i;
    int  nt    = (limit >> 2) + 1;          // tiles of 4 j's

    const float* tmp = tm  + (size_t)row * L * H + (size_t)g * H + c*4;
    const float* Kp  = g_K + (b*L + g)*H + h*D + c*4;
    const float* Vp  = g_V + (b*L + g)*H + h*D + c*4;

    float sum = 0.f;
    float4 accV = make_float4(0.f,0.f,0.f,0.f);
    float4 aS0  = make_float4(0.f,0.f,0.f,0.f);
    float4 aS1  = make_float4(0.f,0.f,0.f,0.f);
    float4 aS2  = make_float4(0.f,0.f,0.f,0.f);
    float4 aS3  = make_float4(0.f,0.f,0.f,0.f);

    #pragma unroll 2
    for (int tI = 0; tI < nt; tI++) {
        float4 t0 = *(const float4*)(tmp);
        float4 t1 = *(const float4*)(tmp + 32);
        float4 t2 = *(const float4*)(tmp + 64);
        float4 t3 = *(const float4*)(tmp + 96);
        float4 k4 = *(const float4*)(Kp);
        float4 v4 = *(const float4*)(Vp);
        tmp += 4*H; Kp += 4*H; Vp += 4*H;

        float p = dot4(qa0,t0) + dot4(qa1,t1) + dot4(qa2,t2) + dot4(qa3,t3)
                + dot4(q4, k4);
        p += __shfl_xor_sync(0xffffffffu, p, 4);
        p += __shfl_xor_sync(0xffffffffu, p, 2);
        p += __shfl_xor_sync(0xffffffffu, p, 1);

        float sc = rmask ? 0.f : p;
        float w  = exp2f(sc);
        int jrow = tI*4 + g;
        w = (jrow <= limit) ? w : 0.f;

        sum += w;
        accV.x += w*v4.x; accV.y += w*v4.y; accV.z += w*v4.z; accV.w += w*v4.w;
        aS0.x += w*t0.x; aS0.y += w*t0.y; aS0.z += w*t0.z; aS0.w += w*t0.w;
        aS1.x += w*t1.x; aS1.y += w*t1.y; aS1.z += w*t1.z; aS1.w += w*t1.w;
        aS2.x += w*t2.x; aS2.y += w*t2.y; aS2.z += w*t2.z; aS2.w += w*t2.w;
        aS3.x += w*t3.x; aS3.y += w*t3.y; aS3.z += w*t3.z; aS3.w += w*t3.w;
    }

    // cross-group sum reduce (over lane bits 3,4)
#define XR(v) { v += __shfl_xor_sync(0xffffffffu, v, 8); \
                v += __shfl_xor_sync(0xffffffffu, v, 16); }
    XR(sum);
    XR(accV.x); XR(accV.y); XR(accV.z); XR(accV.w);
    XR(aS0.x); XR(aS0.y); XR(aS0.z); XR(aS0.w);
    XR(aS1.x); XR(aS1.y); XR(aS1.z); XR(aS1.w);
    XR(aS2.x); XR(aS2.y); XR(aS2.z); XR(aS2.w);
    XR(aS3.x); XR(aS3.y); XR(aS3.z); XR(aS3.w);
#undef XR

    if (g == 0) {
        *(float4*)(&sS[half][h][c*4 +  0]) = aS0;
        *(float4*)(&sS[half][h][c*4 + 32]) = aS1;
        *(float4*)(&sS[half][h][c*4 + 64]) = aS2;
        *(float4*)(&sS[half][h][c*4 + 96]) = aS3;
        *(float4*)(&sV[half][h][c*4]) = accV;
    }
    __syncwarp();

    // epilogue: out[d] = (accV[d] + WA2_h[d,:] . accS) / sum
    const float* wr = WA2 + (h*D + lane)*H;
    float a0 = 0.f, a1 = 0.f;
    #pragma unroll
    for (int k = 0; k < H; k += 8) {
        float4 w0 = *(const float4*)(wr + k);
        float4 s0 = *(const float4*)(&sS[half][h][k]);
        float4 w1 = *(const float4*)(wr + k + 4);
        float4 s1 = *(const float4*)(&sS[half][h][k+4]);
        a0 += w0.x*s0.x + w0.y*s0.y + w0.z*s0.z + w0.w*s0.w;
        a1 += w1.x*s1.x + w1.y*s1.y + w1.z*s1.z + w1.w*s1.w;
    }
    float out = (sV[half][h][lane] + a0 + a1) / sum;
    int idx = row*H + h*D + lane;
    g_x[idx] = g_q[idx] + out;
}

// ---------------- LN2 + FFN + mask (+ optional fused final LN) ---------------
#define FR 4
__global__ __launch_bounds__(128)
void ffn_kernel(const float* __restrict__ lng, const float* __restrict__ lnb,
                const float* __restrict__ c1w, const float* __restrict__ c1b,
                const float* __restrict__ c2w, const float* __restrict__ c2b,
                const unsigned char* __restrict__ tmask,
                float* __restrict__ dst,             // non-null => fused final LN
                const float* __restrict__ lnfg, const float* __restrict__ lnfb)
{
    __shared__ __align__(16) float ys[FR][H];
    __shared__ __align__(16) float hs[FR][H];
    __shared__ float stat[FR][2];
    int t = threadIdx.x;
    int row0 = blockIdx.x * FR;
    int w = t >> 5, lane = t & 31;

    float v[FR];
    #pragma unroll
    for (int r = 0; r < FR; r++) {
        v[r] = g_x[(row0+r)*H + t];
        ys[r][t] = v[r];
    }
    __syncthreads();

    {
        float4 a = *(const float4*)(&ys[w][lane*4]);
        float s  = a.x + a.y + a.z + a.w;
        float sq = a.x*a.x + a.y*a.y + a.z*a.z + a.w*a.w;
        #pragma unroll
        for (int o = 16; o; o >>= 1) {
            s  += __shfl_xor_sync(0xffffffffu, s,  o);
            sq += __shfl_xor_sync(0xffffffffu, sq, o);
        }
        if (lane == 0) {
            float mean = s * (1.0f/H);
            float var  = sq * (1.0f/H) - mean*mean;
            stat[w][0] = mean;
            stat[w][1] = rsqrtf(var + 1e-8f);
        }
    }
    __syncthreads();

    float gam = lng[t], bet = lnb[t];
    float y[FR];
    #pragma unroll
    for (int r = 0; r < FR; r++) {
        y[r] = (v[r] - stat[r][0]) * stat[r][1] * gam + bet;
        ys[r][t] = y[r];
    }
    __syncthreads();

    float acc[FR];
    #pragma unroll
    for (int r = 0; r < FR; r++) acc[r] = 0.f;
    const float* w1r = c1w + t*H;
    #pragma unroll 4
    for (int k = 0; k < H; k += 4) {
        float4 ww = *(const float4*)(w1r + k);
        #pragma unroll
        for (int r = 0; r < FR; r++) {
            float4 yy = *(const float4*)(&ys[r][k]);
            acc[r] += yy.x*ww.x + yy.y*ww.y + yy.z*ww.z + yy.w*ww.w;
        }
    }
    float b1 = c1b[t];
    #pragma unroll
    for (int r = 0; r < FR; r++) hs[r][t] = fmaxf(acc[r] + b1, 0.f);
    __syncthreads();

    #pragma unroll
    for (int r = 0; r < FR; r++) acc[r] = 0.f;
    const float* w2r = c2w + t*H;
    #pragma unroll 4
    for (int k = 0; k < H; k += 4) {
        float4 ww = *(const float4*)(w2r + k);
        #pragma unroll
        for (int r = 0; r < FR; r++) {
            float4 hh = *(const float4*)(&hs[r][k]);
            acc[r] += hh.x*ww.x + hh.y*ww.y + hh.z*ww.z + hh.w*ww.w;
        }
    }
    float b2 = c2b[t];
    float xo[FR];
    #pragma unroll
    for (int r = 0; r < FR; r++) {
        float keep = tmask[row0+r] ? 0.f : 1.f;
        xo[r] = (acc[r] + b2 + y[r]) * keep;
    }

    if (dst == nullptr) {
        #pragma unroll
        for (int r = 0; r < FR; r++) g_x[(row0+r)*H + t] = xo[r];
        return;
    }

    // fused final LayerNorm
    #pragma unroll
    for (int r = 0; r < FR; r++) ys[r][t] = xo[r];
    __syncthreads();
    {
        float4 a = *(const float4*)(&ys[w][lane*4]);
        float s  = a.x + a.y + a.z + a.w;
        float sq = a.x*a.x + a.y*a.y + a.z*a.z + a.w*a.w;
        #pragma unroll
        for (int o = 16; o; o >>= 1) {
            s  += __shfl_xor_sync(0xffffffffu, s,  o);
            sq += __shfl_xor_sync(0xffffffffu, sq, o);
        }
        if (lane == 0) {
            float mean = s * (1.0f/H);
            float var  = sq * (1.0f/H) - mean*mean;
            stat[w][0] = mean;
            stat[w][1] = rsqrtf(var + 1e-8f);
        }
    }
    __syncthreads();
    float fg = lnfg[t], fb = lnfb[t];
    #pragma unroll
    for (int r = 0; r < FR; r++)
        dst[(row0+r)*H + t] = (xo[r] - stat[r][0]) * stat[r][1] * fg + fb;
}

// ---------------- launch -----------------------------------------------------
extern "C" void kernel_launch(void* const* d_in, const int* in_sizes, int n_in,
                              void* d_out, int out_size)
{
    const float*         seqs  = (const float*)d_in[0];
    const unsigned char* tmask = (const unsigned char*)d_in[1];
    const float*         tm    = (const float*)d_in[2];
    const float* Qw  = (const float*)d_in[3];
    const float* Qb  = (const float*)d_in[4];
    const float* Kw  = (const float*)d_in[5];
    const float* Kb  = (const float*)d_in[6];
    const float* Vw  = (const float*)d_in[7];
    const float* Vb  = (const float*)d_in[8];
    const float* WA1 = (const float*)d_in[9];
    const float* WA2 = (const float*)d_in[10];
    const float* ln1g = (const float*)d_in[11];
    const float* ln1b = (const float*)d_in[12];
    const float* ln2g = (const float*)d_in[13];
    const float* ln2b = (const float*)d_in[14];
    const float* c1w  = (const float*)d_in[15];
    const float* c1b  = (const float*)d_in[16];
    const float* c2w  = (const float*)d_in[17];
    const float* c2b  = (const float*)d_in[18];
    const float* lnfg = (const float*)d_in[19];
    const float* lnfb = (const float*)d_in[20];
    float* out = (float*)d_out;

    for (int blk = 0; blk < NB; blk++) {
        qkv_kernel<<<NROWS/RQ, 128>>>(seqs, blk == 0 ? 1 : 0,
                                      ln1g + blk*H, ln1b + blk*H,
                                      Qw + blk*H*H, Qb + blk*H,
                                      Kw + blk*H*H, Kb + blk*H,
                                      Vw + blk*H*H, Vb + blk*H,
                                      WA1 + blk*H*H);
        attn_kernel<<<NROWS/2, 256>>>(tm, tmask, WA2 + blk*H*H);
        ffn_kernel<<<NROWS/FR, 128>>>(ln2g + blk*H, ln2b + blk*H,
                                      c1w + blk*H*H, c1b + blk*H,
                                      c2w + blk*H*H, c2b + blk*H,
                                      tmask,
                                      blk == NB-1 ? out : nullptr,
                                      lnfg, lnfb);
    }
}

// round 11
// speedup vs baseline: 1.0927x; 1.0927x over previous
#include <cuda_runtime.h>
#include <math.h>
#include <float.h>

#define B   8
#define L   256
#define H   128
#define NH  4
#define D   32
#define NB  2
#define NROWS (B*L)

// ---------------- scratch (device globals; no allocation allowed) ------------
__device__ float g_x  [NROWS*H];
__device__ float g_q  [NROWS*H];
__device__ float g_Q  [NROWS*H];      // pre-scaled by log2(e)/sqrt(D)
__device__ float g_K  [NROWS*H];
__device__ float g_V  [NROWS*H];
__device__ float g_QA1[NROWS*NH*H];   // pre-scaled by log2(e)/sqrt(D)

__device__ __forceinline__ float dot4(float4 a, float4 b) {
    return a.x*b.x + a.y*b.y + a.z*b.z + a.w*b.w;
}

// ---------------- LN1 + QKV + QA1 projections (fused), 8 rows/CTA ------------
#define RQ 8
__global__ __launch_bounds__(128)
void qkv_kernel(const float* __restrict__ ext_src, int use_ext,
                const float* __restrict__ lng, const float* __restrict__ lnb,
                const float* __restrict__ Qw, const float* __restrict__ Qb,
                const float* __restrict__ Kw, const float* __restrict__ Kb,
                const float* __restrict__ Vw, const float* __restrict__ Vb,
                const float* __restrict__ WA1)
{
    __shared__ __align__(16) float qs[RQ][H];
    __shared__ __align__(16) float Qs[RQ][H];
    __shared__ float stat[RQ][2];
    int t = threadIdx.x;
    int row0 = blockIdx.x * RQ;
    int w = t >> 5, lane = t & 31;

    float v[RQ];
    #pragma unroll
    for (int r = 0; r < RQ; r++) {
        v[r] = use_ext ? ext_src[(row0+r)*H + t] : g_x[(row0+r)*H + t];
        qs[r][t] = v[r];
    }
    __syncthreads();

    // warp w reduces rows 2w and 2w+1
    #pragma unroll
    for (int rr = 0; rr < 2; rr++) {
        int r = w*2 + rr;
        float4 a = *(const float4*)(&qs[r][lane*4]);
        float s  = a.x + a.y + a.z + a.w;
        float sq = a.x*a.x + a.y*a.y + a.z*a.z + a.w*a.w;
        #pragma unroll
        for (int o = 16; o; o >>= 1) {
            s  += __shfl_xor_sync(0xffffffffu, s,  o);
            sq += __shfl_xor_sync(0xffffffffu, sq, o);
        }
        if (lane == 0) {
            float mean = s * (1.0f/H);
            float var  = sq * (1.0f/H) - mean*mean;
            stat[r][0] = mean;
            stat[r][1] = rsqrtf(var + 1e-8f);
        }
    }
    __syncthreads();

    float gam = lng[t], bet = lnb[t];
    #pragma unroll
    for (int r = 0; r < RQ; r++) {
        float q = (v[r] - stat[r][0]) * stat[r][1] * gam + bet;
        qs[r][t] = q;
        g_q[(row0+r)*H + t] = q;
    }
    __syncthreads();

    float aq[RQ], ak[RQ], av[RQ];
    #pragma unroll
    for (int r = 0; r < RQ; r++) { aq[r] = 0.f; ak[r] = 0.f; av[r] = 0.f; }
    const float* qwr = Qw + t*H;
    const float* kwr = Kw + t*H;
    const float* vwr = Vw + t*H;
    for (int k = 0; k < H; k += 4) {
        float4 wq = *(const float4*)(qwr + k);
        float4 wk = *(const float4*)(kwr + k);
        float4 wv = *(const float4*)(vwr + k);
        #pragma unroll
        for (int r = 0; r < RQ; r++) {
            float4 q4 = *(const float4*)(&qs[r][k]);
            aq[r] += q4.x*wq.x + q4.y*wq.y + q4.z*wq.z + q4.w*wq.w;
            ak[r] += q4.x*wk.x + q4.y*wk.y + q4.z*wk.z + q4.w*wk.w;
            av[r] += q4.x*wv.x + q4.y*wv.y + q4.z*wv.z + q4.w*wv.w;
        }
    }
    // 1/sqrt(32) * log2(e): fixed-base exp2 softmax downstream
    const float rs = 0.17677669529663687f * 1.4426950408889634f;
    float bq = Qb[t], bk = Kb[t], bv = Vb[t];
    #pragma unroll
    for (int r = 0; r < RQ; r++) {
        float Qv = (aq[r] + bq) * rs;
        Qs[r][t] = Qv;
        g_Q[(row0+r)*H + t] = Qv;
        g_K[(row0+r)*H + t] = ak[r] + bk;
        g_V[(row0+r)*H + t] = av[r] + bv;
    }
    __syncthreads();

    #pragma unroll
    for (int h = 0; h < NH; h++) {
        float a[RQ];
        #pragma unroll
        for (int r = 0; r < RQ; r++) a[r] = 0.f;
        const float* w1 = WA1 + h*D*H + t;
        for (int dd = 0; dd < D; dd += 4) {
            float w0 = w1[(dd+0)*H];
            float wA = w1[(dd+1)*H];
            float wB = w1[(dd+2)*H];
            float wC = w1[(dd+3)*H];
            #pragma unroll
            for (int r = 0; r < RQ; r++) {
                float4 q4 = *(const float4*)(&Qs[r][h*D + dd]);
                a[r] += q4.x*w0 + q4.y*wA + q4.z*wB + q4.w*wC;
            }
        }
        #pragma unroll
        for (int r = 0; r < RQ; r++)
            g_QA1[((row0+r)*NH + h)*H + t] = a[r];
    }
}

// ---------------- Attention v6: v3 body, SEQUENTIAL balanced row-pair --------
// CTA k processes rows (b, ii) then (b, L-1-ii) one after the other with the
// proven v3 body (warp = head, 4 j-groups of 8 lanes, fixed-base exp2).
// Total j's per CTA = (ii+1) + (L-ii) = L+1: exactly uniform across the grid.
__global__ __launch_bounds__(128)
void attn_kernel(const float* __restrict__ tm,
                 const unsigned char* __restrict__ tmask,
                 const float* __restrict__ WA2)
{
    __shared__ __align__(16) float sS[NH][H];
    __shared__ __align__(16) float sV[NH][D];
    int kblk = blockIdx.x;
    int b    = kblk >> 7;            // L/2 = 128 pairs per batch
    int ii   = kblk & 127;
    int lane = threadIdx.x & 31;
    int h    = threadIdx.x >> 5;
    int g    = lane >> 3;            // j within tile
    int c    = lane & 7;             // column octet

    #pragma unroll
    for (int rr = 0; rr < 2; rr++) {
        int i   = rr ? (L-1-ii) : ii;
        int row = b*L + i;

        const float* qaB = g_QA1 + (row*NH + h)*H + c*4;
        float4 qa0 = *(const float4*)(qaB);
        float4 qa1 = *(const float4*)(qaB + 32);
        float4 qa2 = *(const float4*)(qaB + 64);
        float4 qa3 = *(const float4*)(qaB + 96);
        float4 q4  = *(const float4*)(g_Q + row*H + h*D + c*4);

        bool rmask = tmask[row] != 0;
        int  limit = rmask ? (L-1) : i;
        int  nt    = (limit >> 2) + 1;          // tiles of 4 j's

        const float* tmp = tm  + (size_t)row * L * H + (size_t)g * H + c*4;
        const float* Kp  = g_K + (b*L + g)*H + h*D + c*4;
        const float* Vp  = g_V + (b*L + g)*H + h*D + c*4;

        float sum = 0.f;
        float4 accV = make_float4(0.f,0.f,0.f,0.f);
        float4 aS0  = make_float4(0.f,0.f,0.f,0.f);
        float4 aS1  = make_float4(0.f,0.f,0.f,0.f);
        float4 aS2  = make_float4(0.f,0.f,0.f,0.f);
        float4 aS3  = make_float4(0.f,0.f,0.f,0.f);

        #pragma unroll 2
        for (int tI = 0; tI < nt; tI++) {
            float4 t0 = *(const float4*)(tmp);
            float4 t1 = *(const float4*)(tmp + 32);
            float4 t2 = *(const float4*)(tmp + 64);
            float4 t3 = *(const float4*)(tmp + 96);
            float4 k4 = *(const float4*)(Kp);
            float4 v4 = *(const float4*)(Vp);
            tmp += 4*H; Kp += 4*H; Vp += 4*H;

            float p = dot4(qa0,t0) + dot4(qa1,t1) + dot4(qa2,t2) + dot4(qa3,t3)
                    + dot4(q4, k4);
            p += __shfl_xor_sync(0xffffffffu, p, 4);
            p += __shfl_xor_sync(0xffffffffu, p, 2);
            p += __shfl_xor_sync(0xffffffffu, p, 1);

            float sc = rmask ? 0.f : p;
            float w  = exp2f(sc);
            int jrow = tI*4 + g;
            w = (jrow <= limit) ? w : 0.f;

            sum += w;
            accV.x += w*v4.x; accV.y += w*v4.y; accV.z += w*v4.z; accV.w += w*v4.w;
            aS0.x += w*t0.x; aS0.y += w*t0.y; aS0.z += w*t0.z; aS0.w += w*t0.w;
            aS1.x += w*t1.x; aS1.y += w*t1.y; aS1.z += w*t1.z; aS1.w += w*t1.w;
            aS2.x += w*t2.x; aS2.y += w*t2.y; aS2.z += w*t2.z; aS2.w += w*t2.w;
            aS3.x += w*t3.x; aS3.y += w*t3.y; aS3.z += w*t3.z; aS3.w += w*t3.w;
        }

        // cross-group sum reduce (over lane bits 3,4)
#define XR(v) { v += __shfl_xor_sync(0xffffffffu, v, 8); \
                v += __shfl_xor_sync(0xffffffffu, v, 16); }
        XR(sum);
        XR(accV.x); XR(accV.y); XR(accV.z); XR(accV.w);
        XR(aS0.x); XR(aS0.y); XR(aS0.z); XR(aS0.w);
        XR(aS1.x); XR(aS1.y); XR(aS1.z); XR(aS1.w);
        XR(aS2.x); XR(aS2.y); XR(aS2.z); XR(aS2.w);
        XR(aS3.x); XR(aS3.y); XR(aS3.z); XR(aS3.w);
#undef XR

        if (g == 0) {
            *(float4*)(&sS[h][c*4 +  0]) = aS0;
            *(float4*)(&sS[h][c*4 + 32]) = aS1;
            *(float4*)(&sS[h][c*4 + 64]) = aS2;
            *(float4*)(&sS[h][c*4 + 96]) = aS3;
            *(float4*)(&sV[h][c*4]) = accV;
        }
        __syncwarp();

        // epilogue: out[d] = (accV[d] + WA2_h[d,:] . accS) / sum
        const float* wr = WA2 + (h*D + lane)*H;
        float a0 = 0.f, a1 = 0.f;
        #pragma unroll
        for (int k = 0; k < H; k += 8) {
            float4 w0 = *(const float4*)(wr + k);
            float4 s0 = *(const float4*)(&sS[h][k]);
            float4 w1 = *(const float4*)(wr + k + 4);
            float4 s1 = *(const float4*)(&sS[h][k+4]);
            a0 += w0.x*s0.x + w0.y*s0.y + w0.z*s0.z + w0.w*s0.w;
            a1 += w1.x*s1.x + w1.y*s1.y + w1.z*s1.z + w1.w*s1.w;
        }
        float out = (sV[h][lane] + a0 + a1) / sum;
        int idx = row*H + h*D + lane;
        g_x[idx] = g_q[idx] + out;
        __syncwarp();
    }
}

// ---------------- LN2 + FFN + mask (+ optional fused final LN) ---------------
#define FR 4
__global__ __launch_bounds__(128)
void ffn_kernel(const float* __restrict__ lng, const float* __restrict__ lnb,
                const float* __restrict__ c1w, const float* __restrict__ c1b,
                const float* __restrict__ c2w, const float* __restrict__ c2b,
                const unsigned char* __restrict__ tmask,
                float* __restrict__ dst,             // non-null => fused final LN
                const float* __restrict__ lnfg, const float* __restrict__ lnfb)
{
    __shared__ __align__(16) float ys[FR][H];
    __shared__ __align__(16) float hs[FR][H];
    __shared__ float stat[FR][2];
    int t = threadIdx.x;
    int row0 = blockIdx.x * FR;
    int w = t >> 5, lane = t & 31;

    float v[FR];
    #pragma unroll
    for (int r = 0; r < FR; r++) {
        v[r] = g_x[(row0+r)*H + t];
        ys[r][t] = v[r];
    }
    __syncthreads();

    {
        float4 a = *(const float4*)(&ys[w][lane*4]);
        float s  = a.x + a.y + a.z + a.w;
        float sq = a.x*a.x + a.y*a.y + a.z*a.z + a.w*a.w;
        #pragma unroll
        for (int o = 16; o; o >>= 1) {
            s  += __shfl_xor_sync(0xffffffffu, s,  o);
            sq += __shfl_xor_sync(0xffffffffu, sq, o);
        }
        if (lane == 0) {
            float mean = s * (1.0f/H);
            float var  = sq * (1.0f/H) - mean*mean;
            stat[w][0] = mean;
            stat[w][1] = rsqrtf(var + 1e-8f);
        }
    }
    __syncthreads();

    float gam = lng[t], bet = lnb[t];
    float y[FR];
    #pragma unroll
    for (int r = 0; r < FR; r++) {
        y[r] = (v[r] - stat[r][0]) * stat[r][1] * gam + bet;
        ys[r][t] = y[r];
    }
    __syncthreads();

    float acc[FR];
    #pragma unroll
    for (int r = 0; r < FR; r++) acc[r] = 0.f;
    const float* w1r = c1w + t*H;
    #pragma unroll 4
    for (int k = 0; k < H; k += 4) {
        float4 ww = *(const float4*)(w1r + k);
        #pragma unroll
        for (int r = 0; r < FR; r++) {
            float4 yy = *(const float4*)(&ys[r][k]);
            acc[r] += yy.x*ww.x + yy.y*ww.y + yy.z*ww.z + yy.w*ww.w;
        }
    }
    float b1 = c1b[t];
    #pragma unroll
    for (int r = 0; r < FR; r++) hs[r][t] = fmaxf(acc[r] + b1, 0.f);
    __syncthreads();

    #pragma unroll
    for (int r = 0; r < FR; r++) acc[r] = 0.f;
    const float* w2r = c2w + t*H;
    #pragma unroll 4
    for (int k = 0; k < H; k += 4) {
        float4 ww = *(const float4*)(w2r + k);
        #pragma unroll
        for (int r = 0; r < FR; r++) {
            float4 hh = *(const float4*)(&hs[r][k]);
            acc[r] += hh.x*ww.x + hh.y*ww.y + hh.z*ww.z + hh.w*ww.w;
        }
    }
    float b2 = c2b[t];
    float xo[FR];
    #pragma unroll
    for (int r = 0; r < FR; r++) {
        float keep = tmask[row0+r] ? 0.f : 1.f;
        xo[r] = (acc[r] + b2 + y[r]) * keep;
    }

    if (dst == nullptr) {
        #pragma unroll
        for (int r = 0; r < FR; r++) g_x[(row0+r)*H + t] = xo[r];
        return;
    }

    // fused final LayerNorm
    #pragma unroll
    for (int r = 0; r < FR; r++) ys[r][t] = xo[r];
    __syncthreads();
    {
        float4 a = *(const float4*)(&ys[w][lane*4]);
        float s  = a.x + a.y + a.z + a.w;
        float sq = a.x*a.x + a.y*a.y + a.z*a.z + a.w*a.w;
        #pragma unroll
        for (int o = 16; o; o >>= 1) {
            s  += __shfl_xor_sync(0xffffffffu, s,  o);
            sq += __shfl_xor_sync(0xffffffffu, sq, o);
        }
        if (lane == 0) {
            float mean = s * (1.0f/H);
            float var  = sq * (1.0f/H) - mean*mean;
            stat[w][0] = mean;
            stat[w][1] = rsqrtf(var + 1e-8f);
        }
    }
    __syncthreads();
    float fg = lnfg[t], fb = lnfb[t];
    #pragma unroll
    for (int r = 0; r < FR; r++)
        dst[(row0+r)*H + t] = (xo[r] - stat[r][0]) * stat[r][1] * fg + fb;
}

// ---------------- launch -----------------------------------------------------
extern "C" void kernel_launch(void* const* d_in, const int* in_sizes, int n_in,
                              void* d_out, int out_size)
{
    const float*         seqs  = (const float*)d_in[0];
    const unsigned char* tmask = (const unsigned char*)d_in[1];
    const float*         tm    = (const float*)d_in[2];
    const float* Qw  = (const float*)d_in[3];
    const float* Qb  = (const float*)d_in[4];
    const float* Kw  = (const float*)d_in[5];
    const float* Kb  = (const float*)d_in[6];
    const float* Vw  = (const float*)d_in[7];
    const float* Vb  = (const float*)d_in[8];
    const float* WA1 = (const float*)d_in[9];
    const float* WA2 = (const float*)d_in[10];
    const float* ln1g = (const float*)d_in[11];
    const float* ln1b = (const float*)d_in[12];
    const float* ln2g = (const float*)d_in[13];
    const float* ln2b = (const float*)d_in[14];
    const float* c1w  = (const float*)d_in[15];
    const float* c1b  = (const float*)d_in[16];
    const float* c2w  = (const float*)d_in[17];
    const float* c2b  = (const float*)d_in[18];
    const float* lnfg = (const float*)d_in[19];
    const float* lnfb = (const float*)d_in[20];
    float* out = (float*)d_out;

    for (int blk = 0; blk < NB; blk++) {
        qkv_kernel<<<NROWS/RQ, 128>>>(seqs, blk == 0 ? 1 : 0,
                                      ln1g + blk*H, ln1b + blk*H,
                                      Qw + blk*H*H, Qb + blk*H,
                                      Kw + blk*H*H, Kb + blk*H,
                                      Vw + blk*H*H, Vb + blk*H,
                                      WA1 + blk*H*H);
        attn_kernel<<<NROWS/2, 128>>>(tm, tmask, WA2 + blk*H*H);
        ffn_kernel<<<NROWS/FR, 128>>>(ln2g + blk*H, ln2b + blk*H,
                                      c1w + blk*H*H, c1b + blk*H,
                                      c2w + blk*H*H, c2b + blk*H,
                                      tmask,
                                      blk == NB-1 ? out : nullptr,
                                      lnfg, lnfb);
    }
}

// round 12
// speedup vs baseline: 1.2645x; 1.1572x over previous
#include <cuda_runtime.h>
#include <math.h>
#include <float.h>

#define B   8
#define L   256
#define H   128
#define NH  4
#define D   32
#define NB  2
#define NROWS (B*L)
#define JT  16   // tm rows staged per cp.async stage

// ---------------- scratch (device globals; no allocation allowed) ------------
__device__ float g_x  [NROWS*H];
__device__ float g_q  [NROWS*H];
__device__ float g_Q  [NROWS*H];      // pre-scaled by log2(e)/sqrt(D)
__device__ float g_K  [NROWS*H];
__device__ float g_V  [NROWS*H];
__device__ float g_QA1[NROWS*NH*H];   // pre-scaled by log2(e)/sqrt(D)

__device__ __forceinline__ float dot4(float4 a, float4 b) {
    return a.x*b.x + a.y*b.y + a.z*b.z + a.w*b.w;
}

// ---------------- LN1 + QKV + QA1 projections (fused), 8 rows/CTA ------------
#define RQ 8
__global__ __launch_bounds__(128)
void qkv_kernel(const float* __restrict__ ext_src, int use_ext,
                const float* __restrict__ lng, const float* __restrict__ lnb,
                const float* __restrict__ Qw, const float* __restrict__ Qb,
                const float* __restrict__ Kw, const float* __restrict__ Kb,
                const float* __restrict__ Vw, const float* __restrict__ Vb,
                const float* __restrict__ WA1)
{
    __shared__ __align__(16) float qs[RQ][H];
    __shared__ __align__(16) float Qs[RQ][H];
    __shared__ float stat[RQ][2];
    int t = threadIdx.x;
    int row0 = blockIdx.x * RQ;
    int w = t >> 5, lane = t & 31;

    float v[RQ];
    #pragma unroll
    for (int r = 0; r < RQ; r++) {
        v[r] = use_ext ? ext_src[(row0+r)*H + t] : g_x[(row0+r)*H + t];
        qs[r][t] = v[r];
    }
    __syncthreads();

    // warp w reduces rows 2w and 2w+1
    #pragma unroll
    for (int rr = 0; rr < 2; rr++) {
        int r = w*2 + rr;
        float4 a = *(const float4*)(&qs[r][lane*4]);
        float s  = a.x + a.y + a.z + a.w;
        float sq = a.x*a.x + a.y*a.y + a.z*a.z + a.w*a.w;
        #pragma unroll
        for (int o = 16; o; o >>= 1) {
            s  += __shfl_xor_sync(0xffffffffu, s,  o);
            sq += __shfl_xor_sync(0xffffffffu, sq, o);
        }
        if (lane == 0) {
            float mean = s * (1.0f/H);
            float var  = sq * (1.0f/H) - mean*mean;
            stat[r][0] = mean;
            stat[r][1] = rsqrtf(var + 1e-8f);
        }
    }
    __syncthreads();

    float gam = lng[t], bet = lnb[t];
    #pragma unroll
    for (int r = 0; r < RQ; r++) {
        float q = (v[r] - stat[r][0]) * stat[r][1] * gam + bet;
        qs[r][t] = q;
        g_q[(row0+r)*H + t] = q;
    }
    __syncthreads();

    float aq[RQ], ak[RQ], av[RQ];
    #pragma unroll
    for (int r = 0; r < RQ; r++) { aq[r] = 0.f; ak[r] = 0.f; av[r] = 0.f; }
    const float* qwr = Qw + t*H;
    const float* kwr = Kw + t*H;
    const float* vwr = Vw + t*H;
    for (int k = 0; k < H; k += 4) {
        float4 wq = *(const float4*)(qwr + k);
        float4 wk = *(const float4*)(kwr + k);
        float4 wv = *(const float4*)(vwr + k);
        #pragma unroll
        for (int r = 0; r < RQ; r++) {
            float4 q4 = *(const float4*)(&qs[r][k]);
            aq[r] += q4.x*wq.x + q4.y*wq.y + q4.z*wq.z + q4.w*wq.w;
            ak[r] += q4.x*wk.x + q4.y*wk.y + q4.z*wk.z + q4.w*wk.w;
            av[r] += q4.x*wv.x + q4.y*wv.y + q4.z*wv.z + q4.w*wv.w;
        }
    }
    // 1/sqrt(32) * log2(e): fixed-base exp2 softmax downstream
    const float rs = 0.17677669529663687f * 1.4426950408889634f;
    float bq = Qb[t], bk = Kb[t], bv = Vb[t];
    #pragma unroll
    for (int r = 0; r < RQ; r++) {
        float Qv = (aq[r] + bq) * rs;
        Qs[r][t] = Qv;
        g_Q[(row0+r)*H + t] = Qv;
        g_K[(row0+r)*H + t] = ak[r] + bk;
        g_V[(row0+r)*H + t] = av[r] + bv;
    }
    __syncthreads();

    #pragma unroll
    for (int h = 0; h < NH; h++) {
        float a[RQ];
        #pragma unroll
        for (int r = 0; r < RQ; r++) a[r] = 0.f;
        const float* w1 = WA1 + h*D*H + t;
        for (int dd = 0; dd < D; dd += 4) {
            float w0 = w1[(dd+0)*H];
            float wA = w1[(dd+1)*H];
            float wB = w1[(dd+2)*H];
            float wC = w1[(dd+3)*H];
            #pragma unroll
            for (int r = 0; r < RQ; r++) {
                float4 q4 = *(const float4*)(&Qs[r][h*D + dd]);
                a[r] += q4.x*w0 + q4.y*wA + q4.z*wB + q4.w*wC;
            }
        }
        #pragma unroll
        for (int r = 0; r < RQ; r++)
            g_QA1[((row0+r)*NH + h)*H + t] = a[r];
    }
}

// ---------------- Attention v7: v6 + cp.async double-buffered tm staging -----
// CTA k processes rows (b, ii) then (b, L-1-ii) sequentially (uniform L+1 j's).
// tm rows stream through smem in 8KB stages (16 rows), 2-deep cp.async pipeline
// (cg = L2-only). Compute = proven v3 body (warp=head, 4 j-groups of 8 lanes,
// fixed-base exp2, no online max).
__global__ __launch_bounds__(128)
void attn_kernel(const float* __restrict__ tm,
                 const unsigned char* __restrict__ tmask,
                 const float* __restrict__ WA2)
{
    __shared__ __align__(16) float sT[2][JT][H];   // 16 KB staging
    __shared__ __align__(16) float sS[NH][H];
    __shared__ __align__(16) float sV[NH][D];
    int kblk = blockIdx.x;
    int b    = kblk >> 7;            // L/2 = 128 pairs per batch
    int ii   = kblk & 127;
    int t    = threadIdx.x;
    int lane = t & 31;
    int h    = t >> 5;
    int g    = lane >> 3;            // j-group within tile
    int c    = lane & 7;             // column octet

    unsigned sbase = (unsigned)__cvta_generic_to_shared(&sT[0][0][0]);

    #pragma unroll
    for (int rr = 0; rr < 2; rr++) {
        int i   = rr ? (L-1-ii) : ii;
        int row = b*L + i;

        const float* qaB = g_QA1 + (row*NH + h)*H + c*4;
        float4 qa0 = *(const float4*)(qaB);
        float4 qa1 = *(const float4*)(qaB + 32);
        float4 qa2 = *(const float4*)(qaB + 64);
        float4 qa3 = *(const float4*)(qaB + 96);
        float4 q4  = *(const float4*)(g_Q + row*H + h*D + c*4);

        bool rmask = tmask[row] != 0;
        int  limit = rmask ? (L-1) : i;
        int  S     = (limit >> 4) + 1;          // stages of JT j's

        const float*  tmrow = tm + (size_t)row * L * H;
        const float*  Kb    = g_K + (size_t)b*L*H + h*D + c*4;
        const float*  Vb    = g_V + (size_t)b*L*H + h*D + c*4;

        float sum = 0.f;
        float4 accV = make_float4(0.f,0.f,0.f,0.f);
        float4 aS0  = make_float4(0.f,0.f,0.f,0.f);
        float4 aS1  = make_float4(0.f,0.f,0.f,0.f);
        float4 aS2  = make_float4(0.f,0.f,0.f,0.f);
        float4 aS3  = make_float4(0.f,0.f,0.f,0.f);

        // ensure previous use of sT is finished (epilogue of rr=0 / prior CTA work)
        __syncthreads();

        // ---- stage loader: 8KB contiguous, 4 x cp.async.128 per thread ----
        #define LOAD_STAGE(s_) {                                            \
            unsigned dstb = sbase + (((s_) & 1) * JT * H + t*4) * 4;        \
            const float4* sp = (const float4*)(tmrow + (size_t)(s_)*JT*H) + t; \
            asm volatile("cp.async.cg.shared.global [%0], [%1], 16;\n"      \
                         "cp.async.cg.shared.global [%2], [%3], 16;\n"      \
                         "cp.async.cg.shared.global [%4], [%5], 16;\n"      \
                         "cp.async.cg.shared.global [%6], [%7], 16;\n"      \
                         "cp.async.commit_group;\n" ::                      \
                         "r"(dstb),          "l"(sp),                       \
                         "r"(dstb + 2048),   "l"(sp + 128),                 \
                         "r"(dstb + 4096),   "l"(sp + 256),                 \
                         "r"(dstb + 6144),   "l"(sp + 384) : "memory"); }

        LOAD_STAGE(0);

        for (int s = 0; s < S; s++) {
            if (s + 1 < S) {
                LOAD_STAGE(s + 1);
                asm volatile("cp.async.wait_group 1;" ::: "memory");
            } else {
                asm volatile("cp.async.wait_group 0;" ::: "memory");
            }
            __syncthreads();

            const float* bufp = &sT[s & 1][0][0];
            #pragma unroll
            for (int k = 0; k < 4; k++) {
                int jl = k*4 + g;
                const float* sr = bufp + jl*H + c*4;
                float4 t0 = *(const float4*)(sr);
                float4 t1 = *(const float4*)(sr + 32);
                float4 t2 = *(const float4*)(sr + 64);
                float4 t3 = *(const float4*)(sr + 96);
                int j = s*JT + jl;
                float4 k4 = *(const float4*)(Kb + (size_t)j*H);
                float4 v4 = *(const float4*)(Vb + (size_t)j*H);

                float p = dot4(qa0,t0) + dot4(qa1,t1) + dot4(qa2,t2) + dot4(qa3,t3)
                        + dot4(q4, k4);
                p += __shfl_xor_sync(0xffffffffu, p, 4);
                p += __shfl_xor_sync(0xffffffffu, p, 2);
                p += __shfl_xor_sync(0xffffffffu, p, 1);

                float sc = rmask ? 0.f : p;
                float w  = exp2f(sc);
                w = (j <= limit) ? w : 0.f;

                sum += w;
                accV.x += w*v4.x; accV.y += w*v4.y; accV.z += w*v4.z; accV.w += w*v4.w;
                aS0.x += w*t0.x; aS0.y += w*t0.y; aS0.z += w*t0.z; aS0.w += w*t0.w;
                aS1.x += w*t1.x; aS1.y += w*t1.y; aS1.z += w*t1.z; aS1.w += w*t1.w;
                aS2.x += w*t2.x; aS2.y += w*t2.y; aS2.z += w*t2.z; aS2.w += w*t2.w;
                aS3.x += w*t3.x; aS3.y += w*t3.y; aS3.z += w*t3.z; aS3.w += w*t3.w;
            }
            __syncthreads();
        }
        #undef LOAD_STAGE

        // cross-group sum reduce (over lane bits 3,4)
#define XR(v) { v += __shfl_xor_sync(0xffffffffu, v, 8); \
                v += __shfl_xor_sync(0xffffffffu, v, 16); }
        XR(sum);
        XR(accV.x); XR(accV.y); XR(accV.z); XR(accV.w);
        XR(aS0.x); XR(aS0.y); XR(aS0.z); XR(aS0.w);
        XR(aS1.x); XR(aS1.y); XR(aS1.z); XR(aS1.w);
        XR(aS2.x); XR(aS2.y); XR(aS2.z); XR(aS2.w);
        XR(aS3.x); XR(aS3.y); XR(aS3.z); XR(aS3.w);
#undef XR

        if (g == 0) {
            *(float4*)(&sS[h][c*4 +  0]) = aS0;
            *(float4*)(&sS[h][c*4 + 32]) = aS1;
            *(float4*)(&sS[h][c*4 + 64]) = aS2;
            *(float4*)(&sS[h][c*4 + 96]) = aS3;
            *(float4*)(&sV[h][c*4]) = accV;
        }
        __syncwarp();

        // epilogue: out[d] = (accV[d] + WA2_h[d,:] . accS) / sum
        const float* wr = WA2 + (h*D + lane)*H;
        float a0 = 0.f, a1 = 0.f;
        #pragma unroll
        for (int k = 0; k < H; k += 8) {
            float4 w0 = *(const float4*)(wr + k);
            float4 s0 = *(const float4*)(&sS[h][k]);
            float4 w1 = *(const float4*)(wr + k + 4);
            float4 s1 = *(const float4*)(&sS[h][k+4]);
            a0 += w0.x*s0.x + w0.y*s0.y + w0.z*s0.z + w0.w*s0.w;
            a1 += w1.x*s1.x + w1.y*s1.y + w1.z*s1.z + w1.w*s1.w;
        }
        float out = (sV[h][lane] + a0 + a1) / sum;
        int idx = row*H + h*D + lane;
        g_x[idx] = g_q[idx] + out;
    }
}

// ---------------- LN2 + FFN + mask (+ optional fused final LN) ---------------
#define FR 4
__global__ __launch_bounds__(128)
void ffn_kernel(const float* __restrict__ lng, const float* __restrict__ lnb,
                const float* __restrict__ c1w, const float* __restrict__ c1b,
                const float* __restrict__ c2w, const float* __restrict__ c2b,
                const unsigned char* __restrict__ tmask,
                float* __restrict__ dst,             // non-null => fused final LN
                const float* __restrict__ lnfg, const float* __restrict__ lnfb)
{
    __shared__ __align__(16) float ys[FR][H];
    __shared__ __align__(16) float hs[FR][H];
    __shared__ float stat[FR][2];
    int t = threadIdx.x;
    int row0 = blockIdx.x * FR;
    int w = t >> 5, lane = t & 31;

    float v[FR];
    #pragma unroll
    for (int r = 0; r < FR; r++) {
        v[r] = g_x[(row0+r)*H + t];
        ys[r][t] = v[r];
    }
    __syncthreads();

    {
        float4 a = *(const float4*)(&ys[w][lane*4]);
        float s  = a.x + a.y + a.z + a.w;
        float sq = a.x*a.x + a.y*a.y + a.z*a.z + a.w*a.w;
        #pragma unroll
        for (int o = 16; o; o >>= 1) {
            s  += __shfl_xor_sync(0xffffffffu, s,  o);
            sq += __shfl_xor_sync(0xffffffffu, sq, o);
        }
        if (lane == 0) {
            float mean = s * (1.0f/H);
            float var  = sq * (1.0f/H) - mean*mean;
            stat[w][0] = mean;
            stat[w][1] = rsqrtf(var + 1e-8f);
        }
    }
    __syncthreads();

    float gam = lng[t], bet = lnb[t];
    float y[FR];
    #pragma unroll
    for (int r = 0; r < FR; r++) {
        y[r] = (v[r] - stat[r][0]) * stat[r][1] * gam + bet;
        ys[r][t] = y[r];
    }
    __syncthreads();

    float acc[FR];
    #pragma unroll
    for (int r = 0; r < FR; r++) acc[r] = 0.f;
    const float* w1r = c1w + t*H;
    #pragma unroll 4
    for (int k = 0; k < H; k += 4) {
        float4 ww = *(const float4*)(w1r + k);
        #pragma unroll
        for (int r = 0; r < FR; r++) {
            float4 yy = *(const float4*)(&ys[r][k]);
            acc[r] += yy.x*ww.x + yy.y*ww.y + yy.z*ww.z + yy.w*ww.w;
        }
    }
    float b1 = c1b[t];
    #pragma unroll
    for (int r = 0; r < FR; r++) hs[r][t] = fmaxf(acc[r] + b1, 0.f);
    __syncthreads();

    #pragma unroll
    for (int r = 0; r < FR; r++) acc[r] = 0.f;
    const float* w2r = c2w + t*H;
    #pragma unroll 4
    for (int k = 0; k < H; k += 4) {
        float4 ww = *(const float4*)(w2r + k);
        #pragma unroll
        for (int r = 0; r < FR; r++) {
            float4 hh = *(const float4*)(&hs[r][k]);
            acc[r] += hh.x*ww.x + hh.y*ww.y + hh.z*ww.z + hh.w*ww.w;
        }
    }
    float b2 = c2b[t];
    float xo[FR];
    #pragma unroll
    for (int r = 0; r < FR; r++) {
        float keep = tmask[row0+r] ? 0.f : 1.f;
        xo[r] = (acc[r] + b2 + y[r]) * keep;
    }

    if (dst == nullptr) {
        #pragma unroll
        for (int r = 0; r < FR; r++) g_x[(row0+r)*H + t] = xo[r];
        return;
    }

    // fused final LayerNorm
    #pragma unroll
    for (int r = 0; r < FR; r++) ys[r][t] = xo[r];
    __syncthreads();
    {
        float4 a = *(const float4*)(&ys[w][lane*4]);
        float s  = a.x + a.y + a.z + a.w;
        float sq = a.x*a.x + a.y*a.y + a.z*a.z + a.w*a.w;
        #pragma unroll
        for (int o = 16; o; o >>= 1) {
            s  += __shfl_xor_sync(0xffffffffu, s,  o);
            sq += __shfl_xor_sync(0xffffffffu, sq, o);
        }
        if (lane == 0) {
            float mean = s * (1.0f/H);
            float var  = sq * (1.0f/H) - mean*mean;
            stat[w][0] = mean;
            stat[w][1] = rsqrtf(var + 1e-8f);
        }
    }
    __syncthreads();
    float fg = lnfg[t], fb = lnfb[t];
    #pragma unroll
    for (int r = 0; r < FR; r++)
        dst[(row0+r)*H + t] = (xo[r] - stat[r][0]) * stat[r][1] * fg + fb;
}

// ---------------- launch -----------------------------------------------------
extern "C" void kernel_launch(void* const* d_in, const int* in_sizes, int n_in,
                              void* d_out, int out_size)
{
    const float*         seqs  = (const float*)d_in[0];
    const unsigned char* tmask = (const unsigned char*)d_in[1];
    const float*         tm    = (const float*)d_in[2];
    const float* Qw  = (const float*)d_in[3];
    const float* Qb  = (const float*)d_in[4];
    const float* Kw  = (const float*)d_in[5];
    const float* Kb  = (const float*)d_in[6];
    const float* Vw  = (const float*)d_in[7];
    const float* Vb  = (const float*)d_in[8];
    const float* WA1 = (const float*)d_in[9];
    const float* WA2 = (const float*)d_in[10];
    const float* ln1g = (const float*)d_in[11];
    const float* ln1b = (const float*)d_in[12];
    const float* ln2g = (const float*)d_in[13];
    const float* ln2b = (const float*)d_in[14];
    const float* c1w  = (const float*)d_in[15];
    const float* c1b  = (const float*)d_in[16];
    const float* c2w  = (const float*)d_in[17];
    const float* c2b  = (const float*)d_in[18];
    const float* lnfg = (const float*)d_in[19];
    const float* lnfb = (const float*)d_in[20];
    float* out = (float*)d_out;

    for (int blk = 0; blk < NB; blk++) {
        qkv_kernel<<<NROWS/RQ, 128>>>(seqs, blk == 0 ? 1 : 0,
                                      ln1g + blk*H, ln1b + blk*H,
                                      Qw + blk*H*H, Qb + blk*H,
                                      Kw + blk*H*H, Kb + blk*H,
                                      Vw + blk*H*H, Vb + blk*H,
                                      WA1 + blk*H*H);
        attn_kernel<<<NROWS/2, 128>>>(tm, tmask, WA2 + blk*H*H);
        ffn_kernel<<<NROWS/FR, 128>>>(ln2g + blk*H, ln2b + blk*H,
                                      c1w + blk*H*H, c1b + blk*H,
                                      c2w + blk*H*H, c2b + blk*H,
                                      tmask,
                                      blk == NB-1 ? out : nullptr,
                                      lnfg, lnfb);
    }
}